// round 1
// baseline (speedup 1.0000x reference)
#include <cuda_runtime.h>

#define SQ 4096
#define EE 512
#define HH 8
#define DD 64

// scratch: q,k,v,attn-out, each 8 heads x 4096 x 64 contiguous fp32 (= flat 4096x512)
__device__ float g_q[HH * SQ * DD];
__device__ float g_k[HH * SQ * DD];
__device__ float g_v[HH * SQ * DD];
__device__ float g_o[HH * SQ * DD];

// ---------------------------------------------------------------------------
// GEMM: C[MxN] = A[MxK] @ W[NxK]^T + bias[N]   (all row-major, NT)
// 64x64 tile, BK=32, 256 threads, 4x4 per thread, float4 smem fragments.
// ---------------------------------------------------------------------------
#define GBM 64
#define GBN 64
#define GBK 32
#define GPAD 68   // 68*4B = 272B row pitch: 16B aligned, conflict-friendly

__global__ void gemm_nt_bias(const float* __restrict__ A, const float* __restrict__ W,
                             const float* __restrict__ bias, float* __restrict__ C,
                             int M, int N, int K) {
    __shared__ float As[GBK][GPAD];   // transposed: As[k][m]
    __shared__ float Ws[GBK][GPAD];   // transposed: Ws[k][n]
    const int tid = threadIdx.x;
    const int tx = tid & 15;
    const int ty = tid >> 4;
    const int m0 = blockIdx.y * GBM;
    const int n0 = blockIdx.x * GBN;
    const int lrow = tid >> 3;          // 0..31
    const int lcol = (tid & 7) << 2;    // 0,4,...,28

    float acc[4][4] = {};

    for (int kt = 0; kt < K; kt += GBK) {
#pragma unroll
        for (int r = 0; r < 2; r++) {
            int row = lrow + 32 * r;
            float4 av = *(const float4*)(A + (size_t)(m0 + row) * K + kt + lcol);
            As[lcol + 0][row] = av.x; As[lcol + 1][row] = av.y;
            As[lcol + 2][row] = av.z; As[lcol + 3][row] = av.w;
            float4 wv = *(const float4*)(W + (size_t)(n0 + row) * K + kt + lcol);
            Ws[lcol + 0][row] = wv.x; Ws[lcol + 1][row] = wv.y;
            Ws[lcol + 2][row] = wv.z; Ws[lcol + 3][row] = wv.w;
        }
        __syncthreads();
#pragma unroll
        for (int kk = 0; kk < GBK; kk++) {
            float4 a = *(const float4*)&As[kk][ty << 2];
            float4 w = *(const float4*)&Ws[kk][tx << 2];
            float av4[4] = {a.x, a.y, a.z, a.w};
            float wv4[4] = {w.x, w.y, w.z, w.w};
#pragma unroll
            for (int i = 0; i < 4; i++)
#pragma unroll
                for (int j = 0; j < 4; j++)
                    acc[i][j] += av4[i] * wv4[j];
        }
        __syncthreads();
    }

    float4 bv = *(const float4*)(bias + n0 + (tx << 2));
    float b4[4] = {bv.x, bv.y, bv.z, bv.w};
#pragma unroll
    for (int i = 0; i < 4; i++) {
        float4 o = make_float4(acc[i][0] + b4[0], acc[i][1] + b4[1],
                               acc[i][2] + b4[2], acc[i][3] + b4[3]);
        *(float4*)(C + (size_t)(m0 + (ty << 2) + i) * N + n0 + (tx << 2)) = o;
    }
}

// ---------------------------------------------------------------------------
// Flash attention, fp32. One block = 64 queries of one head. 256 threads.
// Per-head Q/K/V/O are contiguous 4096x64 row-major (pure-reshape head split).
// ---------------------------------------------------------------------------
#define FPAD 68

__global__ void flash_attn(const float* __restrict__ q, const float* __restrict__ k,
                           const float* __restrict__ v, float* __restrict__ o) {
    extern __shared__ float sm[];
    float (*Qs)[FPAD] = (float(*)[FPAD])(sm);                 // Qs[d][m] (pre-scaled)
    float (*Ks)[FPAD] = (float(*)[FPAD])(sm + 64 * FPAD);     // Ks[d][n]
    float (*Vs)[FPAD] = (float(*)[FPAD])(sm + 2 * 64 * FPAD); // Vs[kv][d]
    float (*Ps)[FPAD] = (float(*)[FPAD])(sm + 3 * 64 * FPAD); // Ps[kv][m]

    const int tid = threadIdx.x;
    const int tx = tid & 15;
    const int ty = tid >> 4;
    const int head = blockIdx.y;
    const int m0 = blockIdx.x * 64;

    const float* Qh = q + (size_t)head * SQ * DD;
    const float* Kh = k + (size_t)head * SQ * DD;
    const float* Vh = v + (size_t)head * SQ * DD;
    float*       Oh = o + (size_t)head * SQ * DD;

    // load Q tile transposed, folding in the 1/sqrt(D)=0.125 scale
#pragma unroll
    for (int it = 0; it < 4; it++) {
        int slot = tid + 256 * it;
        int row = slot >> 4;
        int col = (slot & 15) << 2;
        float4 qv = *(const float4*)(Qh + (size_t)(m0 + row) * DD + col);
        Qs[col + 0][row] = qv.x * 0.125f;
        Qs[col + 1][row] = qv.y * 0.125f;
        Qs[col + 2][row] = qv.z * 0.125f;
        Qs[col + 3][row] = qv.w * 0.125f;
    }

    float acc[4][4] = {};
    float mi[4], li[4];
#pragma unroll
    for (int i = 0; i < 4; i++) { mi[i] = -1e30f; li[i] = 0.f; }

    for (int nt = 0; nt < SQ / 64; nt++) {
        __syncthreads();   // previous tile's PV reads done before K/V overwrite
        const int n0 = nt * 64;
#pragma unroll
        for (int it = 0; it < 4; it++) {
            int slot = tid + 256 * it;
            int row = slot >> 4;
            int col = (slot & 15) << 2;
            float4 kv4 = *(const float4*)(Kh + (size_t)(n0 + row) * DD + col);
            Ks[col + 0][row] = kv4.x; Ks[col + 1][row] = kv4.y;
            Ks[col + 2][row] = kv4.z; Ks[col + 3][row] = kv4.w;
            *(float4*)&Vs[row][col] =
                *(const float4*)(Vh + (size_t)(n0 + row) * DD + col);
        }
        __syncthreads();

        // S = (Q*scale) @ K^T  (4x4 per thread)
        float s[4][4] = {};
#pragma unroll 16
        for (int kk = 0; kk < 64; kk++) {
            float4 a = *(const float4*)&Qs[kk][ty << 2];
            float4 b = *(const float4*)&Ks[kk][tx << 2];
            float av4[4] = {a.x, a.y, a.z, a.w};
            float bv4[4] = {b.x, b.y, b.z, b.w};
#pragma unroll
            for (int i = 0; i < 4; i++)
#pragma unroll
                for (int j = 0; j < 4; j++)
                    s[i][j] += av4[i] * bv4[j];
        }

        // online softmax (row reductions across the 16 tx lanes)
#pragma unroll
        for (int i = 0; i < 4; i++) {
            float rm = fmaxf(fmaxf(s[i][0], s[i][1]), fmaxf(s[i][2], s[i][3]));
#pragma unroll
            for (int off = 8; off; off >>= 1)
                rm = fmaxf(rm, __shfl_xor_sync(0xffffffffu, rm, off, 16));
            float nm = fmaxf(mi[i], rm);
            float al = __expf(mi[i] - nm);
            mi[i] = nm;
            float rs = 0.f;
#pragma unroll
            for (int j = 0; j < 4; j++) {
                s[i][j] = __expf(s[i][j] - nm);
                rs += s[i][j];
            }
#pragma unroll
            for (int off = 8; off; off >>= 1)
                rs += __shfl_xor_sync(0xffffffffu, rs, off, 16);
            li[i] = li[i] * al + rs;
#pragma unroll
            for (int j = 0; j < 4; j++) acc[i][j] *= al;
#pragma unroll
            for (int j = 0; j < 4; j++)
                Ps[(tx << 2) + j][(ty << 2) + i] = s[i][j];
        }
        __syncthreads();   // Ps visible before PV

        // O += P @ V
#pragma unroll 16
        for (int kk = 0; kk < 64; kk++) {
            float4 a = *(const float4*)&Ps[kk][ty << 2];
            float4 b = *(const float4*)&Vs[kk][tx << 2];
            float av4[4] = {a.x, a.y, a.z, a.w};
            float bv4[4] = {b.x, b.y, b.z, b.w};
#pragma unroll
            for (int i = 0; i < 4; i++)
#pragma unroll
                for (int j = 0; j < 4; j++)
                    acc[i][j] += av4[i] * bv4[j];
        }
    }

#pragma unroll
    for (int i = 0; i < 4; i++) {
        float inv = 1.f / li[i];
        float4 ov = make_float4(acc[i][0] * inv, acc[i][1] * inv,
                                acc[i][2] * inv, acc[i][3] * inv);
        *(float4*)(Oh + (size_t)(m0 + (ty << 2) + i) * DD + (tx << 2)) = ov;
    }
}

// ---------------------------------------------------------------------------
extern "C" void kernel_launch(void* const* d_in, const int* in_sizes, int n_in,
                              void* d_out, int out_size) {
    const float* Q    = (const float*)d_in[0];
    const float* K    = (const float*)d_in[1];
    const float* V    = (const float*)d_in[2];
    const float* Wqk  = (const float*)d_in[3];
    const float* bqk  = (const float*)d_in[4];
    const float* Wv   = (const float*)d_in[5];
    const float* bv   = (const float*)d_in[6];
    const float* Wout = (const float*)d_in[7];
    const float* bout = (const float*)d_in[8];
    float* out = (float*)d_out;

    float *qp, *kp, *vp, *op;
    cudaGetSymbolAddress((void**)&qp, g_q);
    cudaGetSymbolAddress((void**)&kp, g_k);
    cudaGetSymbolAddress((void**)&vp, g_v);
    cudaGetSymbolAddress((void**)&op, g_o);

    const int flash_smem = 4 * 64 * FPAD * (int)sizeof(float);  // 69632 B
    cudaFuncSetAttribute(flash_attn, cudaFuncAttributeMaxDynamicSharedMemorySize,
                         flash_smem);

    dim3 gg(EE / GBN, SQ / GBM);  // (8, 64)

    gemm_nt_bias<<<gg, 256>>>(Q, Wqk, bqk, qp, SQ, EE, EE);
    gemm_nt_bias<<<gg, 256>>>(K, Wqk, bqk, kp, SQ, EE, EE);
    gemm_nt_bias<<<gg, 256>>>(V, Wv,  bv,  vp, SQ, EE, EE);
    flash_attn<<<dim3(SQ / 64, HH), 256, flash_smem>>>(qp, kp, vp, op);
    gemm_nt_bias<<<gg, 256>>>(op, Wout, bout, out, SQ, EE, EE);
}

// round 2
// speedup vs baseline: 1.0021x; 1.0021x over previous
#include <cuda_runtime.h>

#define SQ 4096
#define EE 512
#define HH 8
#define DD 64

// scratch: q,k,v,attn-out, each 8 heads x 4096 x 64 contiguous fp32 (= flat 4096x512)
__device__ float g_q[HH * SQ * DD];
__device__ float g_k[HH * SQ * DD];
__device__ float g_v[HH * SQ * DD];
__device__ float g_o[HH * SQ * DD];

// ---------------------------------------------------------------------------
// GEMM: C[MxN] = A[MxK] @ W[NxK]^T + bias[N]   (all row-major, NT)
// 64x64 tile, BK=32, 256 threads, 4x4 per thread, float4 smem fragments.
// ---------------------------------------------------------------------------
#define GBM 64
#define GBN 64
#define GBK 32
#define GPAD 68   // 68*4B = 272B row pitch: 16B aligned, conflict-friendly

__global__ void gemm_nt_bias(const float* __restrict__ A, const float* __restrict__ W,
                             const float* __restrict__ bias, float* __restrict__ C,
                             int M, int N, int K) {
    __shared__ float As[GBK][GPAD];   // transposed: As[k][m]
    __shared__ float Ws[GBK][GPAD];   // transposed: Ws[k][n]
    const int tid = threadIdx.x;
    const int tx = tid & 15;
    const int ty = tid >> 4;
    const int m0 = blockIdx.y * GBM;
    const int n0 = blockIdx.x * GBN;
    const int lrow = tid >> 3;          // 0..31
    const int lcol = (tid & 7) << 2;    // 0,4,...,28

    float acc[4][4] = {};

    for (int kt = 0; kt < K; kt += GBK) {
#pragma unroll
        for (int r = 0; r < 2; r++) {
            int row = lrow + 32 * r;
            float4 av = *(const float4*)(A + (size_t)(m0 + row) * K + kt + lcol);
            As[lcol + 0][row] = av.x; As[lcol + 1][row] = av.y;
            As[lcol + 2][row] = av.z; As[lcol + 3][row] = av.w;
            float4 wv = *(const float4*)(W + (size_t)(n0 + row) * K + kt + lcol);
            Ws[lcol + 0][row] = wv.x; Ws[lcol + 1][row] = wv.y;
            Ws[lcol + 2][row] = wv.z; Ws[lcol + 3][row] = wv.w;
        }
        __syncthreads();
#pragma unroll
        for (int kk = 0; kk < GBK; kk++) {
            float4 a = *(const float4*)&As[kk][ty << 2];
            float4 w = *(const float4*)&Ws[kk][tx << 2];
            float av4[4] = {a.x, a.y, a.z, a.w};
            float wv4[4] = {w.x, w.y, w.z, w.w};
#pragma unroll
            for (int i = 0; i < 4; i++)
#pragma unroll
                for (int j = 0; j < 4; j++)
                    acc[i][j] += av4[i] * wv4[j];
        }
        __syncthreads();
    }

    float4 bv = *(const float4*)(bias + n0 + (tx << 2));
    float b4[4] = {bv.x, bv.y, bv.z, bv.w};
#pragma unroll
    for (int i = 0; i < 4; i++) {
        float4 o = make_float4(acc[i][0] + b4[0], acc[i][1] + b4[1],
                               acc[i][2] + b4[2], acc[i][3] + b4[3]);
        *(float4*)(C + (size_t)(m0 + (ty << 2) + i) * N + n0 + (tx << 2)) = o;
    }
}

// ---------------------------------------------------------------------------
// Flash attention, fp32. One block = 64 queries of one head. 256 threads.
// Per-head Q/K/V/O are contiguous 4096x64 row-major (pure-reshape head split).
// ---------------------------------------------------------------------------
#define FPAD 68

__global__ void flash_attn(const float* __restrict__ q, const float* __restrict__ k,
                           const float* __restrict__ v, float* __restrict__ o) {
    extern __shared__ float sm[];
    float (*Qs)[FPAD] = (float(*)[FPAD])(sm);                 // Qs[d][m] (pre-scaled)
    float (*Ks)[FPAD] = (float(*)[FPAD])(sm + 64 * FPAD);     // Ks[d][n]
    float (*Vs)[FPAD] = (float(*)[FPAD])(sm + 2 * 64 * FPAD); // Vs[kv][d]
    float (*Ps)[FPAD] = (float(*)[FPAD])(sm + 3 * 64 * FPAD); // Ps[kv][m]

    const int tid = threadIdx.x;
    const int tx = tid & 15;
    const int ty = tid >> 4;
    const int head = blockIdx.y;
    const int m0 = blockIdx.x * 64;

    const float* Qh = q + (size_t)head * SQ * DD;
    const float* Kh = k + (size_t)head * SQ * DD;
    const float* Vh = v + (size_t)head * SQ * DD;
    float*       Oh = o + (size_t)head * SQ * DD;

    // load Q tile transposed, folding in the 1/sqrt(D)=0.125 scale
#pragma unroll
    for (int it = 0; it < 4; it++) {
        int slot = tid + 256 * it;
        int row = slot >> 4;
        int col = (slot & 15) << 2;
        float4 qv = *(const float4*)(Qh + (size_t)(m0 + row) * DD + col);
        Qs[col + 0][row] = qv.x * 0.125f;
        Qs[col + 1][row] = qv.y * 0.125f;
        Qs[col + 2][row] = qv.z * 0.125f;
        Qs[col + 3][row] = qv.w * 0.125f;
    }

    float acc[4][4] = {};
    float mi[4], li[4];
#pragma unroll
    for (int i = 0; i < 4; i++) { mi[i] = -1e30f; li[i] = 0.f; }

    for (int nt = 0; nt < SQ / 64; nt++) {
        __syncthreads();   // previous tile's PV reads done before K/V overwrite
        const int n0 = nt * 64;
#pragma unroll
        for (int it = 0; it < 4; it++) {
            int slot = tid + 256 * it;
            int row = slot >> 4;
            int col = (slot & 15) << 2;
            float4 kv4 = *(const float4*)(Kh + (size_t)(n0 + row) * DD + col);
            Ks[col + 0][row] = kv4.x; Ks[col + 1][row] = kv4.y;
            Ks[col + 2][row] = kv4.z; Ks[col + 3][row] = kv4.w;
            *(float4*)&Vs[row][col] =
                *(const float4*)(Vh + (size_t)(n0 + row) * DD + col);
        }
        __syncthreads();

        // S = (Q*scale) @ K^T  (4x4 per thread)
        float s[4][4] = {};
#pragma unroll 16
        for (int kk = 0; kk < 64; kk++) {
            float4 a = *(const float4*)&Qs[kk][ty << 2];
            float4 b = *(const float4*)&Ks[kk][tx << 2];
            float av4[4] = {a.x, a.y, a.z, a.w};
            float bv4[4] = {b.x, b.y, b.z, b.w};
#pragma unroll
            for (int i = 0; i < 4; i++)
#pragma unroll
                for (int j = 0; j < 4; j++)
                    s[i][j] += av4[i] * bv4[j];
        }

        // online softmax (row reductions across the 16 tx lanes)
#pragma unroll
        for (int i = 0; i < 4; i++) {
            float rm = fmaxf(fmaxf(s[i][0], s[i][1]), fmaxf(s[i][2], s[i][3]));
#pragma unroll
            for (int off = 8; off; off >>= 1)
                rm = fmaxf(rm, __shfl_xor_sync(0xffffffffu, rm, off, 16));
            float nm = fmaxf(mi[i], rm);
            float al = __expf(mi[i] - nm);
            mi[i] = nm;
            float rs = 0.f;
#pragma unroll
            for (int j = 0; j < 4; j++) {
                s[i][j] = __expf(s[i][j] - nm);
                rs += s[i][j];
            }
#pragma unroll
            for (int off = 8; off; off >>= 1)
                rs += __shfl_xor_sync(0xffffffffu, rs, off, 16);
            li[i] = li[i] * al + rs;
#pragma unroll
            for (int j = 0; j < 4; j++) acc[i][j] *= al;
#pragma unroll
            for (int j = 0; j < 4; j++)
                Ps[(tx << 2) + j][(ty << 2) + i] = s[i][j];
        }
        __syncthreads();   // Ps visible before PV

        // O += P @ V
#pragma unroll 16
        for (int kk = 0; kk < 64; kk++) {
            float4 a = *(const float4*)&Ps[kk][ty << 2];
            float4 b = *(const float4*)&Vs[kk][tx << 2];
            float av4[4] = {a.x, a.y, a.z, a.w};
            float bv4[4] = {b.x, b.y, b.z, b.w};
#pragma unroll
            for (int i = 0; i < 4; i++)
#pragma unroll
                for (int j = 0; j < 4; j++)
                    acc[i][j] += av4[i] * bv4[j];
        }
    }

#pragma unroll
    for (int i = 0; i < 4; i++) {
        float inv = 1.f / li[i];
        float4 ov = make_float4(acc[i][0] * inv, acc[i][1] * inv,
                                acc[i][2] * inv, acc[i][3] * inv);
        *(float4*)(Oh + (size_t)(m0 + (ty << 2) + i) * DD + (tx << 2)) = ov;
    }
}

// ---------------------------------------------------------------------------
extern "C" void kernel_launch(void* const* d_in, const int* in_sizes, int n_in,
                              void* d_out, int out_size) {
    const float* Q    = (const float*)d_in[0];
    const float* K    = (const float*)d_in[1];
    const float* V    = (const float*)d_in[2];
    const float* Wqk  = (const float*)d_in[3];
    const float* bqk  = (const float*)d_in[4];
    const float* Wv   = (const float*)d_in[5];
    const float* bv   = (const float*)d_in[6];
    const float* Wout = (const float*)d_in[7];
    const float* bout = (const float*)d_in[8];
    float* out = (float*)d_out;

    float *qp, *kp, *vp, *op;
    cudaGetSymbolAddress((void**)&qp, g_q);
    cudaGetSymbolAddress((void**)&kp, g_k);
    cudaGetSymbolAddress((void**)&vp, g_v);
    cudaGetSymbolAddress((void**)&op, g_o);

    const int flash_smem = 4 * 64 * FPAD * (int)sizeof(float);  // 69632 B
    cudaFuncSetAttribute(flash_attn, cudaFuncAttributeMaxDynamicSharedMemorySize,
                         flash_smem);

    dim3 gg(EE / GBN, SQ / GBM);  // (8, 64)

    gemm_nt_bias<<<gg, 256>>>(Q, Wqk, bqk, qp, SQ, EE, EE);
    gemm_nt_bias<<<gg, 256>>>(K, Wqk, bqk, kp, SQ, EE, EE);
    gemm_nt_bias<<<gg, 256>>>(V, Wv,  bv,  vp, SQ, EE, EE);
    flash_attn<<<dim3(SQ / 64, HH), 256, flash_smem>>>(qp, kp, vp, op);
    gemm_nt_bias<<<gg, 256>>>(op, Wout, bout, out, SQ, EE, EE);
}

// round 4
// speedup vs baseline: 2.6408x; 2.6353x over previous
#include <cuda_runtime.h>
#include <cuda_bf16.h>
#include <cstdint>

#define SQ 4096
#define EE 512
#define HH 8
#define DD 64
#define HSZ (SQ*DD)
#define TOT (SQ*EE)

// ------------------- global scratch -------------------
__device__ float g_qf[TOT], g_kf[TOT], g_vf[TOT], g_of[TOT];
__device__ __nv_bfloat16 g_Qhi[TOT], g_Qlo[TOT], g_Khi[TOT], g_Klo[TOT], g_Vhi[TOT], g_Vlo[TOT];
__device__ __nv_bfloat16 g_W1hi[EE*EE], g_W1lo[EE*EE];
__device__ __nv_bfloat16 g_W2hi[EE*EE], g_W2lo[EE*EE];
__device__ __nv_bfloat16 g_W3hi[EE*EE], g_W3lo[EE*EE];
__device__ __nv_bfloat16 g_qhi[TOT], g_qlo[TOT], g_khi[TOT], g_klo[TOT];
__device__ __nv_bfloat16 g_vthi[TOT], g_vtlo[TOT], g_ohi[TOT], g_olo[TOT];

// ------------------- helpers -------------------
__device__ __forceinline__ uint32_t smem_u32(const void* p) {
    uint32_t a;
    asm("{ .reg .u64 t; cvta.to.shared.u64 t, %1; cvt.u32.u64 %0, t; }" : "=r"(a) : "l"(p));
    return a;
}

#define LDSM4(R0,R1,R2,R3,ADDR) \
    asm volatile("ldmatrix.sync.aligned.m8n8.x4.shared.b16 {%0,%1,%2,%3}, [%4];" \
        : "=r"(R0),"=r"(R1),"=r"(R2),"=r"(R3) : "r"(ADDR))

#define MMA16816(C,A,B) \
    asm volatile("mma.sync.aligned.m16n8k16.row.col.f32.bf16.bf16.f32 " \
        "{%0,%1,%2,%3},{%4,%5,%6,%7},{%8,%9},{%0,%1,%2,%3};" \
        : "+f"((C)[0]),"+f"((C)[1]),"+f"((C)[2]),"+f"((C)[3]) \
        : "r"((A)[0]),"r"((A)[1]),"r"((A)[2]),"r"((A)[3]),"r"((B)[0]),"r"((B)[1]))

// ------------------- elementwise hi/lo split -------------------
__global__ void split4(const float4* __restrict__ x, uint2* __restrict__ hi,
                       uint2* __restrict__ lo, float scale) {
    int i = blockIdx.x * blockDim.x + threadIdx.x;
    float4 v = x[i];
    v.x *= scale; v.y *= scale; v.z *= scale; v.w *= scale;
    __nv_bfloat162 h01 = __floats2bfloat162_rn(v.x, v.y);
    __nv_bfloat162 h23 = __floats2bfloat162_rn(v.z, v.w);
    __nv_bfloat162 l01 = __floats2bfloat162_rn(v.x - __bfloat162float(h01.x),
                                               v.y - __bfloat162float(h01.y));
    __nv_bfloat162 l23 = __floats2bfloat162_rn(v.z - __bfloat162float(h23.x),
                                               v.w - __bfloat162float(h23.y));
    uint2 hv, lv;
    hv.x = *(uint32_t*)&h01; hv.y = *(uint32_t*)&h23;
    lv.x = *(uint32_t*)&l01; lv.y = *(uint32_t*)&l23;
    hi[i] = hv; lo[i] = lv;
}

// per-head transpose of V: [h][4096][64] -> [h][64][4096], split hi/lo
__global__ void vtrans_split(const float* __restrict__ vf,
                             __nv_bfloat16* __restrict__ vthi,
                             __nv_bfloat16* __restrict__ vtlo) {
    __shared__ float tile[32][33];
    int h = blockIdx.z, t0 = blockIdx.x * 32, d0 = blockIdx.y * 32;
    int tx = threadIdx.x, ty = threadIdx.y;
    tile[ty][tx] = vf[(size_t)h * HSZ + (size_t)(t0 + ty) * DD + d0 + tx];
    __syncthreads();
    float v = tile[tx][ty];
    __nv_bfloat16 hh = __float2bfloat16(v);
    __nv_bfloat16 ll = __float2bfloat16(v - __bfloat162float(hh));
    size_t o = (size_t)h * HSZ + (size_t)(d0 + ty) * SQ + t0 + tx;
    vthi[o] = hh; vtlo[o] = ll;
}

// ------------------- mma.sync GEMM: C[4096x512] = A @ W^T + b -------------------
// block 128x128, 8 warps as 4(m) x 2(n): warp tile 32x64. K-chunk 32.
#define GPITCH 40                       // bf16 elems per row (80B, ldmatrix conflict-free)
#define GSZ (128*GPITCH*2)              // 10240 B per matrix
#define G_SMEM (4*GSZ)                  // 40960 B

__global__ void __launch_bounds__(256) gemm_mma(
    const __nv_bfloat16* __restrict__ Ahi, const __nv_bfloat16* __restrict__ Alo,
    const __nv_bfloat16* __restrict__ Whi, const __nv_bfloat16* __restrict__ Wlo,
    const float* __restrict__ bias, float* __restrict__ C)
{
    extern __shared__ char sm[];
    uint32_t sb = smem_u32(sm);
    int tid = threadIdx.x, wid = tid >> 5, lane = tid & 31;
    int wm = wid & 3, wn = wid >> 2;
    int m0 = blockIdx.y * 128, n0 = blockIdx.x * 128;
    int l15 = lane & 15, lh = lane >> 4;

    float acc[2][8][4] = {};

    for (int ch = 0; ch < 16; ch++) {
        __syncthreads();
#pragma unroll
        for (int q = 0; q < 8; q++) {
            int id = q * 256 + tid;
            int mat = id >> 9, rem = id & 511, row = rem >> 2, col = rem & 3;
            const __nv_bfloat16* g =
                (mat == 0 ? Ahi : mat == 1 ? Alo : mat == 2 ? Whi : Wlo)
                + (size_t)((mat < 2 ? m0 : n0) + row) * EE + ch * 32 + col * 8;
            *(uint4*)(sm + mat * GSZ + row * (GPITCH * 2) + col * 16) = *(const uint4*)g;
        }
        __syncthreads();
#pragma unroll
        for (int ks = 0; ks < 2; ks++) {
            uint32_t ah[2][4], al[2][4];
#pragma unroll
            for (int mt = 0; mt < 2; mt++) {
                uint32_t addr = sb + (wm * 32 + mt * 16 + l15) * (GPITCH * 2)
                              + (ks * 16 + 8 * lh) * 2;
                LDSM4(ah[mt][0], ah[mt][1], ah[mt][2], ah[mt][3], addr);
                addr += GSZ;
                LDSM4(al[mt][0], al[mt][1], al[mt][2], al[mt][3], addr);
            }
            uint32_t bh[8][2], bl[8][2];
#pragma unroll
            for (int jt = 0; jt < 4; jt++) {
                uint32_t addr = sb + 2 * GSZ + (wn * 64 + jt * 16 + l15) * (GPITCH * 2)
                              + (ks * 16 + 8 * lh) * 2;
                uint32_t r0, r1, r2, r3;
                LDSM4(r0, r1, r2, r3, addr);
                bh[2*jt][0] = r0; bh[2*jt+1][0] = r1; bh[2*jt][1] = r2; bh[2*jt+1][1] = r3;
                addr += GSZ;
                LDSM4(r0, r1, r2, r3, addr);
                bl[2*jt][0] = r0; bl[2*jt+1][0] = r1; bl[2*jt][1] = r2; bl[2*jt+1][1] = r3;
            }
#pragma unroll
            for (int mt = 0; mt < 2; mt++)
#pragma unroll
                for (int j = 0; j < 8; j++) {
                    MMA16816(acc[mt][j], ah[mt], bh[j]);
                    MMA16816(acc[mt][j], ah[mt], bl[j]);
                    MMA16816(acc[mt][j], al[mt], bh[j]);
                }
        }
    }

    int r = lane >> 2, c2 = (lane & 3) * 2;
#pragma unroll
    for (int mt = 0; mt < 2; mt++) {
        float* crow = C + (size_t)(m0 + wm * 32 + mt * 16 + r) * EE + n0 + wn * 64;
#pragma unroll
        for (int j = 0; j < 8; j++) {
            float b0 = __ldg(bias + n0 + wn * 64 + j * 8 + c2);
            float b1 = __ldg(bias + n0 + wn * 64 + j * 8 + c2 + 1);
            *(float2*)(crow + j * 8 + c2) = make_float2(acc[mt][j][0] + b0, acc[mt][j][1] + b1);
            *(float2*)(crow + 8 * EE + j * 8 + c2) = make_float2(acc[mt][j][2] + b0, acc[mt][j][3] + b1);
        }
    }
}

// ------------------- mma.sync flash attention -------------------
// block = 128 queries of one head, 8 warps (16 rows each). KV chunk 64.
// Q frags in registers; S/exp/P in registers; K & Vt hi/lo staged in smem.
#define APITCH 72                       // 144B pitch, ldmatrix conflict-free
#define AMSZ (64*APITCH*2)              // 9216 B per matrix
#define A_SMEM (4*AMSZ)                 // 36864 B

__global__ void __launch_bounds__(256) attn_mma(
    const __nv_bfloat16* __restrict__ qhi, const __nv_bfloat16* __restrict__ qlo,
    const __nv_bfloat16* __restrict__ khi, const __nv_bfloat16* __restrict__ klo,
    const __nv_bfloat16* __restrict__ vth, const __nv_bfloat16* __restrict__ vtl,
    float* __restrict__ of)
{
    extern __shared__ char sm[];
    uint32_t sb = smem_u32(sm);
    int tid = threadIdx.x, wid = tid >> 5, lane = tid & 31;
    int head = blockIdx.y, m0 = blockIdx.x * 128;
    const size_t hb = (size_t)head * HSZ;
    int r = lane >> 2, c2 = (lane & 3) * 2;
    int l15 = lane & 15, lh = lane >> 4;

    // Q fragments (hi/lo), held in registers for all 64 KV chunks
    uint32_t qh[4][4], ql[4][4];
    {
        const __nv_bfloat16* q0h = qhi + hb + (size_t)(m0 + wid * 16) * DD;
        const __nv_bfloat16* q0l = qlo + hb + (size_t)(m0 + wid * 16) * DD;
#pragma unroll
        for (int ks = 0; ks < 4; ks++)
#pragma unroll
            for (int j = 0; j < 4; j++) {
                int rr = r + (j & 1) * 8;
                int kk = ks * 16 + c2 + (j >> 1) * 8;
                qh[ks][j] = *(const uint32_t*)(q0h + rr * DD + kk);
                ql[ks][j] = *(const uint32_t*)(q0l + rr * DD + kk);
            }
    }

    float oacc[8][4] = {};
    float rs0 = 0.f, rs1 = 0.f;

    for (int t = 0; t < 64; t++) {
        int t0 = t * 64;
        __syncthreads();
#pragma unroll
        for (int q = 0; q < 8; q++) {
            int id = q * 256 + tid;
            int mat = id >> 9, rem = id & 511, row = rem >> 3, col = rem & 7;
            const __nv_bfloat16* g;
            if (mat == 0)      g = khi + hb + (size_t)(t0 + row) * DD + col * 8;
            else if (mat == 1) g = klo + hb + (size_t)(t0 + row) * DD + col * 8;
            else if (mat == 2) g = vth + hb + (size_t)row * SQ + t0 + col * 8;
            else               g = vtl + hb + (size_t)row * SQ + t0 + col * 8;
            *(uint4*)(sm + mat * AMSZ + row * (APITCH * 2) + col * 16) = *(const uint4*)g;
        }
        __syncthreads();

        // ---- S = Q @ K^T (3-term) ----
        float sacc[8][4] = {};
#pragma unroll
        for (int ks = 0; ks < 4; ks++) {
            uint32_t bh[8][2], bl[8][2];
#pragma unroll
            for (int jt = 0; jt < 4; jt++) {
                uint32_t addr = sb + (jt * 16 + l15) * (APITCH * 2) + (ks * 16 + 8 * lh) * 2;
                uint32_t r0, r1, r2, r3;
                LDSM4(r0, r1, r2, r3, addr);
                bh[2*jt][0] = r0; bh[2*jt+1][0] = r1; bh[2*jt][1] = r2; bh[2*jt+1][1] = r3;
                addr += AMSZ;
                LDSM4(r0, r1, r2, r3, addr);
                bl[2*jt][0] = r0; bl[2*jt+1][0] = r1; bl[2*jt][1] = r2; bl[2*jt+1][1] = r3;
            }
#pragma unroll
            for (int j = 0; j < 8; j++) {
                MMA16816(sacc[j], qh[ks], bh[j]);
                MMA16816(sacc[j], qh[ks], bl[j]);
                MMA16816(sacc[j], ql[ks], bh[j]);
            }
        }

        // ---- unnormalized softmax: exp + rowsum + pack hi/lo A-frags ----
#pragma unroll
        for (int j = 0; j < 8; j++) {
#pragma unroll
            for (int e = 0; e < 4; e++) sacc[j][e] = __expf(sacc[j][e]);
            rs0 += sacc[j][0] + sacc[j][1];
            rs1 += sacc[j][2] + sacc[j][3];
        }
        uint32_t pa[4][4], pl[4][4];
#pragma unroll
        for (int tt = 0; tt < 4; tt++)
#pragma unroll
            for (int idx = 0; idx < 4; idx++) {
                int j = 2 * tt + (idx >> 1);
                float p0 = sacc[j][(idx & 1) * 2], p1 = sacc[j][(idx & 1) * 2 + 1];
                __nv_bfloat162 h = __floats2bfloat162_rn(p0, p1);
                __nv_bfloat162 l = __floats2bfloat162_rn(p0 - __bfloat162float(h.x),
                                                         p1 - __bfloat162float(h.y));
                pa[tt][idx] = *(uint32_t*)&h;
                pl[tt][idx] = *(uint32_t*)&l;
            }

        // ---- O += P @ V (3-term, B = Vt k-contiguous) ----
#pragma unroll
        for (int tt = 0; tt < 4; tt++) {
            uint32_t vh[8][2], vl[8][2];
#pragma unroll
            for (int jt = 0; jt < 4; jt++) {
                uint32_t addr = sb + 2 * AMSZ + (jt * 16 + l15) * (APITCH * 2)
                              + (tt * 16 + 8 * lh) * 2;
                uint32_t r0, r1, r2, r3;
                LDSM4(r0, r1, r2, r3, addr);
                vh[2*jt][0] = r0; vh[2*jt+1][0] = r1; vh[2*jt][1] = r2; vh[2*jt+1][1] = r3;
                addr += AMSZ;
                LDSM4(r0, r1, r2, r3, addr);
                vl[2*jt][0] = r0; vl[2*jt+1][0] = r1; vl[2*jt][1] = r2; vl[2*jt+1][1] = r3;
            }
#pragma unroll
            for (int j = 0; j < 8; j++) {
                MMA16816(oacc[j], pa[tt], vh[j]);
                MMA16816(oacc[j], pa[tt], vl[j]);
                MMA16816(oacc[j], pl[tt], vh[j]);
            }
        }
    }

    // rowsum reduce across the quad (lanes sharing the same r)
    rs0 += __shfl_xor_sync(0xffffffffu, rs0, 1);
    rs0 += __shfl_xor_sync(0xffffffffu, rs0, 2);
    rs1 += __shfl_xor_sync(0xffffffffu, rs1, 1);
    rs1 += __shfl_xor_sync(0xffffffffu, rs1, 2);
    float i0 = 1.f / rs0, i1 = 1.f / rs1;

    float* orow = of + hb + (size_t)(m0 + wid * 16 + r) * DD;
#pragma unroll
    for (int j = 0; j < 8; j++) {
        *(float2*)(orow + j * 8 + c2) =
            make_float2(oacc[j][0] * i0, oacc[j][1] * i0);
        *(float2*)(orow + 8 * DD + j * 8 + c2) =
            make_float2(oacc[j][2] * i1, oacc[j][3] * i1);
    }
}

// ------------------- host -------------------
extern "C" void kernel_launch(void* const* d_in, const int* in_sizes, int n_in,
                              void* d_out, int out_size) {
    const float* Q    = (const float*)d_in[0];
    const float* K    = (const float*)d_in[1];
    const float* V    = (const float*)d_in[2];
    const float* Wqk  = (const float*)d_in[3];
    const float* bqk  = (const float*)d_in[4];
    const float* Wv   = (const float*)d_in[5];
    const float* bv   = (const float*)d_in[6];
    const float* Wout = (const float*)d_in[7];
    const float* bout = (const float*)d_in[8];
    float* out = (float*)d_out;

    float *qf, *kf, *vf, *ofp;
    __nv_bfloat16 *Qhi,*Qlo,*Khi,*Klo,*Vhi,*Vlo,*W1h,*W1l,*W2h,*W2l,*W3h,*W3l;
    __nv_bfloat16 *qhi,*qlo,*khi,*klo,*vth,*vtl,*ohi,*olo;
    cudaGetSymbolAddress((void**)&qf, g_qf);   cudaGetSymbolAddress((void**)&kf, g_kf);
    cudaGetSymbolAddress((void**)&vf, g_vf);   cudaGetSymbolAddress((void**)&ofp, g_of);
    cudaGetSymbolAddress((void**)&Qhi, g_Qhi); cudaGetSymbolAddress((void**)&Qlo, g_Qlo);
    cudaGetSymbolAddress((void**)&Khi, g_Khi); cudaGetSymbolAddress((void**)&Klo, g_Klo);
    cudaGetSymbolAddress((void**)&Vhi, g_Vhi); cudaGetSymbolAddress((void**)&Vlo, g_Vlo);
    cudaGetSymbolAddress((void**)&W1h, g_W1hi); cudaGetSymbolAddress((void**)&W1l, g_W1lo);
    cudaGetSymbolAddress((void**)&W2h, g_W2hi); cudaGetSymbolAddress((void**)&W2l, g_W2lo);
    cudaGetSymbolAddress((void**)&W3h, g_W3hi); cudaGetSymbolAddress((void**)&W3l, g_W3lo);
    cudaGetSymbolAddress((void**)&qhi, g_qhi); cudaGetSymbolAddress((void**)&qlo, g_qlo);
    cudaGetSymbolAddress((void**)&khi, g_khi); cudaGetSymbolAddress((void**)&klo, g_klo);
    cudaGetSymbolAddress((void**)&vth, g_vthi); cudaGetSymbolAddress((void**)&vtl, g_vtlo);
    cudaGetSymbolAddress((void**)&ohi, g_ohi); cudaGetSymbolAddress((void**)&olo, g_olo);

    const int TB = 256;
    split4<<<TOT/4/TB, TB>>>((const float4*)Q, (uint2*)Qhi, (uint2*)Qlo, 1.f);
    split4<<<TOT/4/TB, TB>>>((const float4*)K, (uint2*)Khi, (uint2*)Klo, 1.f);
    split4<<<TOT/4/TB, TB>>>((const float4*)V, (uint2*)Vhi, (uint2*)Vlo, 1.f);
    split4<<<EE*EE/4/TB, TB>>>((const float4*)Wqk,  (uint2*)W1h, (uint2*)W1l, 1.f);
    split4<<<EE*EE/4/TB, TB>>>((const float4*)Wv,   (uint2*)W2h, (uint2*)W2l, 1.f);
    split4<<<EE*EE/4/TB, TB>>>((const float4*)Wout, (uint2*)W3h, (uint2*)W3l, 1.f);

    dim3 gg(EE/128, SQ/128);   // (4, 32)
    gemm_mma<<<gg, TB, G_SMEM>>>(Qhi, Qlo, W1h, W1l, bqk, qf);
    gemm_mma<<<gg, TB, G_SMEM>>>(Khi, Klo, W1h, W1l, bqk, kf);
    gemm_mma<<<gg, TB, G_SMEM>>>(Vhi, Vlo, W2h, W2l, bv,  vf);

    split4<<<TOT/4/TB, TB>>>((const float4*)qf, (uint2*)qhi, (uint2*)qlo, 0.125f);
    split4<<<TOT/4/TB, TB>>>((const float4*)kf, (uint2*)khi, (uint2*)klo, 1.f);
    vtrans_split<<<dim3(SQ/32, DD/32, HH), dim3(32,32)>>>(vf, vth, vtl);

    attn_mma<<<dim3(SQ/128, HH), TB, A_SMEM>>>(qhi, qlo, khi, klo, vth, vtl, ofp);

    split4<<<TOT/4/TB, TB>>>((const float4*)ofp, (uint2*)ohi, (uint2*)olo, 1.f);
    gemm_mma<<<gg, TB, G_SMEM>>>(ohi, olo, W3h, W3l, bout, out);
}

// round 5
// speedup vs baseline: 2.8665x; 1.0855x over previous
#include <cuda_runtime.h>
#include <cuda_bf16.h>
#include <cstdint>

#define SQ 4096
#define EE 512
#define HH 8
#define DD 64
#define HSZ (SQ*DD)
#define TOT (SQ*EE)

// ------------------- global scratch -------------------
__device__ float g_vf[TOT];
__device__ __nv_bfloat16 g_Qhi[TOT], g_Qlo[TOT], g_Khi[TOT], g_Klo[TOT], g_Vhi[TOT], g_Vlo[TOT];
__device__ __nv_bfloat16 g_W1hi[EE*EE], g_W1lo[EE*EE];
__device__ __nv_bfloat16 g_W2hi[EE*EE], g_W2lo[EE*EE];
__device__ __nv_bfloat16 g_W3hi[EE*EE], g_W3lo[EE*EE];
__device__ __nv_bfloat16 g_qhi[TOT], g_qlo[TOT], g_khi[TOT], g_klo[TOT];
__device__ __nv_bfloat16 g_vthi[TOT], g_vtlo[TOT], g_ohi[TOT], g_olo[TOT];

// ------------------- helpers -------------------
__device__ __forceinline__ uint32_t smem_u32(const void* p) {
    uint32_t a;
    asm("{ .reg .u64 t; cvta.to.shared.u64 t, %1; cvt.u32.u64 %0, t; }" : "=r"(a) : "l"(p));
    return a;
}
#define LDSM4(R0,R1,R2,R3,ADDR) \
    asm volatile("ldmatrix.sync.aligned.m8n8.x4.shared.b16 {%0,%1,%2,%3}, [%4];" \
        : "=r"(R0),"=r"(R1),"=r"(R2),"=r"(R3) : "r"(ADDR))
#define MMA16816(C,A,B) \
    asm volatile("mma.sync.aligned.m16n8k16.row.col.f32.bf16.bf16.f32 " \
        "{%0,%1,%2,%3},{%4,%5,%6,%7},{%8,%9},{%0,%1,%2,%3};" \
        : "+f"((C)[0]),"+f"((C)[1]),"+f"((C)[2]),"+f"((C)[3]) \
        : "r"((A)[0]),"r"((A)[1]),"r"((A)[2]),"r"((A)[3]),"r"((B)[0]),"r"((B)[1]))
#define CPA16(DST,SRC) \
    asm volatile("cp.async.cg.shared.global [%0], [%1], 16;" :: "r"(DST), "l"(SRC) : "memory")
#define CPC() asm volatile("cp.async.commit_group;" ::: "memory")
#define CPW(N) asm volatile("cp.async.wait_group %0;" :: "n"(N) : "memory")

// ------------------- elementwise hi/lo split -------------------
__global__ void split4(const float4* __restrict__ x, uint2* __restrict__ hi,
                       uint2* __restrict__ lo, float scale) {
    int i = blockIdx.x * blockDim.x + threadIdx.x;
    float4 v = x[i];
    v.x *= scale; v.y *= scale; v.z *= scale; v.w *= scale;
    __nv_bfloat162 h01 = __floats2bfloat162_rn(v.x, v.y);
    __nv_bfloat162 h23 = __floats2bfloat162_rn(v.z, v.w);
    __nv_bfloat162 l01 = __floats2bfloat162_rn(v.x - __bfloat162float(h01.x),
                                               v.y - __bfloat162float(h01.y));
    __nv_bfloat162 l23 = __floats2bfloat162_rn(v.z - __bfloat162float(h23.x),
                                               v.w - __bfloat162float(h23.y));
    uint2 hv, lv;
    hv.x = *(uint32_t*)&h01; hv.y = *(uint32_t*)&h23;
    lv.x = *(uint32_t*)&l01; lv.y = *(uint32_t*)&l23;
    hi[i] = hv; lo[i] = lv;
}

// per-head transpose of V: [h][4096][64] -> [h][64][4096], split hi/lo
__global__ void vtrans_split(const float* __restrict__ vf,
                             __nv_bfloat16* __restrict__ vthi,
                             __nv_bfloat16* __restrict__ vtlo) {
    __shared__ float tile[32][33];
    int h = blockIdx.z, t0 = blockIdx.x * 32, d0 = blockIdx.y * 32;
    int tx = threadIdx.x, ty = threadIdx.y;
    tile[ty][tx] = vf[(size_t)h * HSZ + (size_t)(t0 + ty) * DD + d0 + tx];
    __syncthreads();
    float v = tile[tx][ty];
    __nv_bfloat16 hh = __float2bfloat16(v);
    __nv_bfloat16 ll = __float2bfloat16(v - __bfloat162float(hh));
    size_t o = (size_t)h * HSZ + (size_t)(d0 + ty) * SQ + t0 + tx;
    vthi[o] = hh; vtlo[o] = ll;
}

// ------------------- mma.sync GEMM (cp.async 2-stage, fused split epilogue) ----
#define GPITCH 40
#define GSZ (128*GPITCH*2)              // 10240 B / matrix
#define GSTG (4*GSZ)                    // 40960 B / stage
#define G_SMEM (2*GSTG)                 // 81920 B

__device__ __forceinline__ void gemm_prefetch(
    uint32_t sb, int stage, int tid, int m0, int n0, int ch,
    const __nv_bfloat16* Ahi, const __nv_bfloat16* Alo,
    const __nv_bfloat16* Whi, const __nv_bfloat16* Wlo)
{
#pragma unroll
    for (int q = 0; q < 8; q++) {
        int id = q * 256 + tid;
        int mat = id >> 9, rem = id & 511, row = rem >> 2, col = rem & 3;
        const __nv_bfloat16* g =
            (mat == 0 ? Ahi : mat == 1 ? Alo : mat == 2 ? Whi : Wlo)
            + (size_t)((mat < 2 ? m0 : n0) + row) * EE + ch * 32 + col * 8;
        CPA16(sb + stage * GSTG + mat * GSZ + row * (GPITCH * 2) + col * 16, g);
    }
}

__global__ void __launch_bounds__(256) gemm_mma(
    const __nv_bfloat16* __restrict__ Ahi, const __nv_bfloat16* __restrict__ Alo,
    const __nv_bfloat16* __restrict__ Whi, const __nv_bfloat16* __restrict__ Wlo,
    const float* __restrict__ bias, float* __restrict__ C,
    __nv_bfloat16* __restrict__ Chi, __nv_bfloat16* __restrict__ Clo, float scale)
{
    extern __shared__ char sm[];
    uint32_t sb = smem_u32(sm);
    int tid = threadIdx.x, wid = tid >> 5, lane = tid & 31;
    int wm = wid & 3, wn = wid >> 2;
    int m0 = blockIdx.y * 128, n0 = blockIdx.x * 128;
    int l15 = lane & 15, lh = lane >> 4;

    float acc[2][8][4] = {};

    gemm_prefetch(sb, 0, tid, m0, n0, 0, Ahi, Alo, Whi, Wlo);
    CPC();

    for (int ch = 0; ch < 16; ch++) {
        if (ch < 15) {
            gemm_prefetch(sb, (ch + 1) & 1, tid, m0, n0, ch + 1, Ahi, Alo, Whi, Wlo);
            CPC();
            CPW(1);
        } else {
            CPW(0);
        }
        __syncthreads();
        uint32_t sbs = sb + (ch & 1) * GSTG;
#pragma unroll
        for (int ks = 0; ks < 2; ks++) {
            uint32_t ah[2][4], al[2][4];
#pragma unroll
            for (int mt = 0; mt < 2; mt++) {
                uint32_t addr = sbs + (wm * 32 + mt * 16 + l15) * (GPITCH * 2)
                              + (ks * 16 + 8 * lh) * 2;
                LDSM4(ah[mt][0], ah[mt][1], ah[mt][2], ah[mt][3], addr);
                addr += GSZ;
                LDSM4(al[mt][0], al[mt][1], al[mt][2], al[mt][3], addr);
            }
            uint32_t bh[8][2], bl[8][2];
#pragma unroll
            for (int jt = 0; jt < 4; jt++) {
                uint32_t addr = sbs + 2 * GSZ + (wn * 64 + jt * 16 + l15) * (GPITCH * 2)
                              + (ks * 16 + 8 * lh) * 2;
                uint32_t r0, r1, r2, r3;
                LDSM4(r0, r1, r2, r3, addr);
                bh[2*jt][0] = r0; bh[2*jt+1][0] = r1; bh[2*jt][1] = r2; bh[2*jt+1][1] = r3;
                addr += GSZ;
                LDSM4(r0, r1, r2, r3, addr);
                bl[2*jt][0] = r0; bl[2*jt+1][0] = r1; bl[2*jt][1] = r2; bl[2*jt+1][1] = r3;
            }
#pragma unroll
            for (int mt = 0; mt < 2; mt++)
#pragma unroll
                for (int j = 0; j < 8; j++) {
                    MMA16816(acc[mt][j], ah[mt], bh[j]);
                    MMA16816(acc[mt][j], ah[mt], bl[j]);
                    MMA16816(acc[mt][j], al[mt], bh[j]);
                }
        }
        __syncthreads();
    }

    int r = lane >> 2, c2 = (lane & 3) * 2;
#pragma unroll
    for (int mt = 0; mt < 2; mt++) {
        size_t rbase = (size_t)(m0 + wm * 32 + mt * 16 + r) * EE + n0 + wn * 64;
#pragma unroll
        for (int j = 0; j < 8; j++) {
            float b0 = __ldg(bias + n0 + wn * 64 + j * 8 + c2);
            float b1 = __ldg(bias + n0 + wn * 64 + j * 8 + c2 + 1);
            float y00 = (acc[mt][j][0] + b0) * scale, y01 = (acc[mt][j][1] + b1) * scale;
            float y10 = (acc[mt][j][2] + b0) * scale, y11 = (acc[mt][j][3] + b1) * scale;
            if (Chi) {
                __nv_bfloat162 h0 = __floats2bfloat162_rn(y00, y01);
                __nv_bfloat162 l0 = __floats2bfloat162_rn(y00 - __bfloat162float(h0.x),
                                                          y01 - __bfloat162float(h0.y));
                __nv_bfloat162 h1 = __floats2bfloat162_rn(y10, y11);
                __nv_bfloat162 l1 = __floats2bfloat162_rn(y10 - __bfloat162float(h1.x),
                                                          y11 - __bfloat162float(h1.y));
                *(uint32_t*)(Chi + rbase + j * 8 + c2)          = *(uint32_t*)&h0;
                *(uint32_t*)(Clo + rbase + j * 8 + c2)          = *(uint32_t*)&l0;
                *(uint32_t*)(Chi + rbase + 8 * EE + j * 8 + c2) = *(uint32_t*)&h1;
                *(uint32_t*)(Clo + rbase + 8 * EE + j * 8 + c2) = *(uint32_t*)&l1;
            } else {
                *(float2*)(C + rbase + j * 8 + c2)          = make_float2(y00, y01);
                *(float2*)(C + rbase + 8 * EE + j * 8 + c2) = make_float2(y10, y11);
            }
        }
    }
}

// ------------------- mma.sync flash attention (cp.async 2-stage) -------------------
#define APITCH 72
#define AMSZ (64*APITCH*2)              // 9216 B / matrix
#define ASTG (4*AMSZ)                   // 36864 B / stage
#define A_SMEM (2*ASTG)                 // 73728 B

__device__ __forceinline__ void attn_prefetch(
    uint32_t sb, int stage, int tid, size_t hb, int t0,
    const __nv_bfloat16* khi, const __nv_bfloat16* klo,
    const __nv_bfloat16* vth, const __nv_bfloat16* vtl)
{
#pragma unroll
    for (int q = 0; q < 8; q++) {
        int id = q * 256 + tid;
        int mat = id >> 9, rem = id & 511, row = rem >> 3, col = rem & 7;
        const __nv_bfloat16* g;
        if (mat == 0)      g = khi + hb + (size_t)(t0 + row) * DD + col * 8;
        else if (mat == 1) g = klo + hb + (size_t)(t0 + row) * DD + col * 8;
        else if (mat == 2) g = vth + hb + (size_t)row * SQ + t0 + col * 8;
        else               g = vtl + hb + (size_t)row * SQ + t0 + col * 8;
        CPA16(sb + stage * ASTG + mat * AMSZ + row * (APITCH * 2) + col * 16, g);
    }
}

__global__ void __launch_bounds__(256) attn_mma(
    const __nv_bfloat16* __restrict__ qhi, const __nv_bfloat16* __restrict__ qlo,
    const __nv_bfloat16* __restrict__ khi, const __nv_bfloat16* __restrict__ klo,
    const __nv_bfloat16* __restrict__ vth, const __nv_bfloat16* __restrict__ vtl,
    __nv_bfloat16* __restrict__ ohi, __nv_bfloat16* __restrict__ olo)
{
    extern __shared__ char sm[];
    uint32_t sb = smem_u32(sm);
    int tid = threadIdx.x, wid = tid >> 5, lane = tid & 31;
    int head = blockIdx.y, m0 = blockIdx.x * 128;
    const size_t hb = (size_t)head * HSZ;
    int r = lane >> 2, c2 = (lane & 3) * 2;
    int l15 = lane & 15, lh = lane >> 4;

    attn_prefetch(sb, 0, tid, hb, 0, khi, klo, vth, vtl);
    CPC();

    // Q fragments (hi/lo), held in registers for all 64 KV chunks
    uint32_t qh[4][4], ql[4][4];
    {
        const __nv_bfloat16* q0h = qhi + hb + (size_t)(m0 + wid * 16) * DD;
        const __nv_bfloat16* q0l = qlo + hb + (size_t)(m0 + wid * 16) * DD;
#pragma unroll
        for (int ks = 0; ks < 4; ks++)
#pragma unroll
            for (int j = 0; j < 4; j++) {
                int rr = r + (j & 1) * 8;
                int kk = ks * 16 + c2 + (j >> 1) * 8;
                qh[ks][j] = *(const uint32_t*)(q0h + rr * DD + kk);
                ql[ks][j] = *(const uint32_t*)(q0l + rr * DD + kk);
            }
    }

    float oacc[8][4] = {};
    float rs0 = 0.f, rs1 = 0.f;

    for (int t = 0; t < 64; t++) {
        if (t < 63) {
            attn_prefetch(sb, (t + 1) & 1, tid, hb, (t + 1) * 64, khi, klo, vth, vtl);
            CPC();
            CPW(1);
        } else {
            CPW(0);
        }
        __syncthreads();
        uint32_t sbs = sb + (t & 1) * ASTG;

        // ---- S = Q @ K^T (3-term) ----
        float sacc[8][4] = {};
#pragma unroll
        for (int ks = 0; ks < 4; ks++) {
            uint32_t bh[8][2], bl[8][2];
#pragma unroll
            for (int jt = 0; jt < 4; jt++) {
                uint32_t addr = sbs + (jt * 16 + l15) * (APITCH * 2) + (ks * 16 + 8 * lh) * 2;
                uint32_t r0, r1, r2, r3;
                LDSM4(r0, r1, r2, r3, addr);
                bh[2*jt][0] = r0; bh[2*jt+1][0] = r1; bh[2*jt][1] = r2; bh[2*jt+1][1] = r3;
                addr += AMSZ;
                LDSM4(r0, r1, r2, r3, addr);
                bl[2*jt][0] = r0; bl[2*jt+1][0] = r1; bl[2*jt][1] = r2; bl[2*jt+1][1] = r3;
            }
#pragma unroll
            for (int j = 0; j < 8; j++) {
                MMA16816(sacc[j], qh[ks], bh[j]);
                MMA16816(sacc[j], qh[ks], bl[j]);
                MMA16816(sacc[j], ql[ks], bh[j]);
            }
        }

        // ---- unnormalized softmax: exp + rowsum + pack hi/lo A-frags ----
#pragma unroll
        for (int j = 0; j < 8; j++) {
#pragma unroll
            for (int e = 0; e < 4; e++) sacc[j][e] = __expf(sacc[j][e]);
            rs0 += sacc[j][0] + sacc[j][1];
            rs1 += sacc[j][2] + sacc[j][3];
        }
        uint32_t pa[4][4], pl[4][4];
#pragma unroll
        for (int tt = 0; tt < 4; tt++)
#pragma unroll
            for (int idx = 0; idx < 4; idx++) {
                int j = 2 * tt + (idx >> 1);
                float p0 = sacc[j][(idx & 1) * 2], p1 = sacc[j][(idx & 1) * 2 + 1];
                __nv_bfloat162 h = __floats2bfloat162_rn(p0, p1);
                __nv_bfloat162 l = __floats2bfloat162_rn(p0 - __bfloat162float(h.x),
                                                         p1 - __bfloat162float(h.y));
                pa[tt][idx] = *(uint32_t*)&h;
                pl[tt][idx] = *(uint32_t*)&l;
            }

        // ---- O += P @ V (3-term, B = Vt k-contiguous) ----
#pragma unroll
        for (int tt = 0; tt < 4; tt++) {
            uint32_t vh[8][2], vl[8][2];
#pragma unroll
            for (int jt = 0; jt < 4; jt++) {
                uint32_t addr = sbs + 2 * AMSZ + (jt * 16 + l15) * (APITCH * 2)
                              + (tt * 16 + 8 * lh) * 2;
                uint32_t r0, r1, r2, r3;
                LDSM4(r0, r1, r2, r3, addr);
                vh[2*jt][0] = r0; vh[2*jt+1][0] = r1; vh[2*jt][1] = r2; vh[2*jt+1][1] = r3;
                addr += AMSZ;
                LDSM4(r0, r1, r2, r3, addr);
                vl[2*jt][0] = r0; vl[2*jt+1][0] = r1; vl[2*jt][1] = r2; vl[2*jt+1][1] = r3;
            }
#pragma unroll
            for (int j = 0; j < 8; j++) {
                MMA16816(oacc[j], pa[tt], vh[j]);
                MMA16816(oacc[j], pa[tt], vl[j]);
                MMA16816(oacc[j], pl[tt], vh[j]);
            }
        }
        __syncthreads();
    }

    // rowsum reduce across the quad
    rs0 += __shfl_xor_sync(0xffffffffu, rs0, 1);
    rs0 += __shfl_xor_sync(0xffffffffu, rs0, 2);
    rs1 += __shfl_xor_sync(0xffffffffu, rs1, 1);
    rs1 += __shfl_xor_sync(0xffffffffu, rs1, 2);
    float i0 = 1.f / rs0, i1 = 1.f / rs1;

    size_t rbase = hb + (size_t)(m0 + wid * 16 + r) * DD;
#pragma unroll
    for (int j = 0; j < 8; j++) {
        float y00 = oacc[j][0] * i0, y01 = oacc[j][1] * i0;
        float y10 = oacc[j][2] * i1, y11 = oacc[j][3] * i1;
        __nv_bfloat162 h0 = __floats2bfloat162_rn(y00, y01);
        __nv_bfloat162 l0 = __floats2bfloat162_rn(y00 - __bfloat162float(h0.x),
                                                  y01 - __bfloat162float(h0.y));
        __nv_bfloat162 h1 = __floats2bfloat162_rn(y10, y11);
        __nv_bfloat162 l1 = __floats2bfloat162_rn(y10 - __bfloat162float(h1.x),
                                                  y11 - __bfloat162float(h1.y));
        *(uint32_t*)(ohi + rbase + j * 8 + c2)          = *(uint32_t*)&h0;
        *(uint32_t*)(olo + rbase + j * 8 + c2)          = *(uint32_t*)&l0;
        *(uint32_t*)(ohi + rbase + 8 * DD + j * 8 + c2) = *(uint32_t*)&h1;
        *(uint32_t*)(olo + rbase + 8 * DD + j * 8 + c2) = *(uint32_t*)&l1;
    }
}

// ------------------- host -------------------
extern "C" void kernel_launch(void* const* d_in, const int* in_sizes, int n_in,
                              void* d_out, int out_size) {
    const float* Q    = (const float*)d_in[0];
    const float* K    = (const float*)d_in[1];
    const float* V    = (const float*)d_in[2];
    const float* Wqk  = (const float*)d_in[3];
    const float* bqk  = (const float*)d_in[4];
    const float* Wv   = (const float*)d_in[5];
    const float* bv   = (const float*)d_in[6];
    const float* Wout = (const float*)d_in[7];
    const float* bout = (const float*)d_in[8];
    float* out = (float*)d_out;

    float *vf;
    __nv_bfloat16 *Qhi,*Qlo,*Khi,*Klo,*Vhi,*Vlo,*W1h,*W1l,*W2h,*W2l,*W3h,*W3l;
    __nv_bfloat16 *qhi,*qlo,*khi,*klo,*vth,*vtl,*ohi,*olo;
    cudaGetSymbolAddress((void**)&vf, g_vf);
    cudaGetSymbolAddress((void**)&Qhi, g_Qhi); cudaGetSymbolAddress((void**)&Qlo, g_Qlo);
    cudaGetSymbolAddress((void**)&Khi, g_Khi); cudaGetSymbolAddress((void**)&Klo, g_Klo);
    cudaGetSymbolAddress((void**)&Vhi, g_Vhi); cudaGetSymbolAddress((void**)&Vlo, g_Vlo);
    cudaGetSymbolAddress((void**)&W1h, g_W1hi); cudaGetSymbolAddress((void**)&W1l, g_W1lo);
    cudaGetSymbolAddress((void**)&W2h, g_W2hi); cudaGetSymbolAddress((void**)&W2l, g_W2lo);
    cudaGetSymbolAddress((void**)&W3h, g_W3hi); cudaGetSymbolAddress((void**)&W3l, g_W3lo);
    cudaGetSymbolAddress((void**)&qhi, g_qhi); cudaGetSymbolAddress((void**)&qlo, g_qlo);
    cudaGetSymbolAddress((void**)&khi, g_khi); cudaGetSymbolAddress((void**)&klo, g_klo);
    cudaGetSymbolAddress((void**)&vth, g_vthi); cudaGetSymbolAddress((void**)&vtl, g_vtlo);
    cudaGetSymbolAddress((void**)&ohi, g_ohi); cudaGetSymbolAddress((void**)&olo, g_olo);

    cudaFuncSetAttribute(gemm_mma, cudaFuncAttributeMaxDynamicSharedMemorySize, G_SMEM);
    cudaFuncSetAttribute(attn_mma, cudaFuncAttributeMaxDynamicSharedMemorySize, A_SMEM);

    const int TB = 256;
    split4<<<TOT/4/TB, TB>>>((const float4*)Q, (uint2*)Qhi, (uint2*)Qlo, 1.f);
    split4<<<TOT/4/TB, TB>>>((const float4*)K, (uint2*)Khi, (uint2*)Klo, 1.f);
    split4<<<TOT/4/TB, TB>>>((const float4*)V, (uint2*)Vhi, (uint2*)Vlo, 1.f);
    split4<<<EE*EE/4/TB, TB>>>((const float4*)Wqk,  (uint2*)W1h, (uint2*)W1l, 1.f);
    split4<<<EE*EE/4/TB, TB>>>((const float4*)Wv,   (uint2*)W2h, (uint2*)W2l, 1.f);
    split4<<<EE*EE/4/TB, TB>>>((const float4*)Wout, (uint2*)W3h, (uint2*)W3l, 1.f);

    dim3 gg(EE/128, SQ/128);   // (4, 32)
    // q = (Q@Wqk^T + b) * 0.125, fused split -> qhi/qlo
    gemm_mma<<<gg, TB, G_SMEM>>>(Qhi, Qlo, W1h, W1l, bqk, nullptr, qhi, qlo, 0.125f);
    gemm_mma<<<gg, TB, G_SMEM>>>(Khi, Klo, W1h, W1l, bqk, nullptr, khi, klo, 1.f);
    gemm_mma<<<gg, TB, G_SMEM>>>(Vhi, Vlo, W2h, W2l, bv,  vf, nullptr, nullptr, 1.f);

    vtrans_split<<<dim3(SQ/32, DD/32, HH), dim3(32,32)>>>(vf, vth, vtl);

    attn_mma<<<dim3(SQ/128, HH), TB, A_SMEM>>>(qhi, qlo, khi, klo, vth, vtl, ohi, olo);

    gemm_mma<<<gg, TB, G_SMEM>>>(ohi, olo, W3h, W3l, bout, out, nullptr, nullptr, 1.f);
}

// round 6
// speedup vs baseline: 3.1905x; 1.1130x over previous
#include <cuda_runtime.h>
#include <cuda_bf16.h>
#include <cstdint>

#define SQ 4096
#define EE 512
#define HH 8
#define DD 64
#define HSZ (SQ*DD)
#define TOT (SQ*EE)

// ------------------- global scratch -------------------
__device__ float g_vf[TOT];
__device__ __nv_bfloat16 g_Qhi[TOT], g_Qlo[TOT], g_Khi[TOT], g_Klo[TOT], g_Vhi[TOT], g_Vlo[TOT];
__device__ __nv_bfloat16 g_W1hi[EE*EE], g_W1lo[EE*EE];
__device__ __nv_bfloat16 g_W2hi[EE*EE], g_W2lo[EE*EE];
__device__ __nv_bfloat16 g_W3hi[EE*EE], g_W3lo[EE*EE];
__device__ __nv_bfloat16 g_qhi[TOT], g_qlo[TOT], g_khi[TOT], g_klo[TOT];
__device__ __nv_bfloat16 g_vthi[TOT], g_vtlo[TOT], g_ohi[TOT], g_olo[TOT];

// ------------------- helpers -------------------
__device__ __forceinline__ uint32_t smem_u32(const void* p) {
    uint32_t a;
    asm("{ .reg .u64 t; cvta.to.shared.u64 t, %1; cvt.u32.u64 %0, t; }" : "=r"(a) : "l"(p));
    return a;
}
#define LDSM4(R0,R1,R2,R3,ADDR) \
    asm volatile("ldmatrix.sync.aligned.m8n8.x4.shared.b16 {%0,%1,%2,%3}, [%4];" \
        : "=r"(R0),"=r"(R1),"=r"(R2),"=r"(R3) : "r"(ADDR))
#define MMA16816(C,A,B) \
    asm volatile("mma.sync.aligned.m16n8k16.row.col.f32.bf16.bf16.f32 " \
        "{%0,%1,%2,%3},{%4,%5,%6,%7},{%8,%9},{%0,%1,%2,%3};" \
        : "+f"((C)[0]),"+f"((C)[1]),"+f"((C)[2]),"+f"((C)[3]) \
        : "r"((A)[0]),"r"((A)[1]),"r"((A)[2]),"r"((A)[3]),"r"((B)[0]),"r"((B)[1]))
#define CPA16(DST,SRC) \
    asm volatile("cp.async.cg.shared.global [%0], [%1], 16;" :: "r"(DST), "l"(SRC) : "memory")
#define CPC() asm volatile("cp.async.commit_group;" ::: "memory")
#define CPW(N) asm volatile("cp.async.wait_group %0;" :: "n"(N) : "memory")

// ------------------- elementwise hi/lo split (3 tensors per launch) ----------
__global__ void split4x3(const float4* __restrict__ x0, uint2* __restrict__ h0, uint2* __restrict__ l0,
                         const float4* __restrict__ x1, uint2* __restrict__ h1, uint2* __restrict__ l1,
                         const float4* __restrict__ x2, uint2* __restrict__ h2, uint2* __restrict__ l2) {
    const float4* x = blockIdx.y == 0 ? x0 : blockIdx.y == 1 ? x1 : x2;
    uint2* hi = blockIdx.y == 0 ? h0 : blockIdx.y == 1 ? h1 : h2;
    uint2* lo = blockIdx.y == 0 ? l0 : blockIdx.y == 1 ? l1 : l2;
    int i = blockIdx.x * blockDim.x + threadIdx.x;
    float4 v = x[i];
    __nv_bfloat162 a01 = __floats2bfloat162_rn(v.x, v.y);
    __nv_bfloat162 a23 = __floats2bfloat162_rn(v.z, v.w);
    __nv_bfloat162 b01 = __floats2bfloat162_rn(v.x - __bfloat162float(a01.x),
                                               v.y - __bfloat162float(a01.y));
    __nv_bfloat162 b23 = __floats2bfloat162_rn(v.z - __bfloat162float(a23.x),
                                               v.w - __bfloat162float(a23.y));
    uint2 hv, lv;
    hv.x = *(uint32_t*)&a01; hv.y = *(uint32_t*)&a23;
    lv.x = *(uint32_t*)&b01; lv.y = *(uint32_t*)&b23;
    hi[i] = hv; lo[i] = lv;
}

// per-head transpose of V: [h][4096][64] -> [h][64][4096], split hi/lo
__global__ void vtrans_split(const float* __restrict__ vf,
                             __nv_bfloat16* __restrict__ vthi,
                             __nv_bfloat16* __restrict__ vtlo) {
    __shared__ float tile[32][33];
    int h = blockIdx.z, t0 = blockIdx.x * 32, d0 = blockIdx.y * 32;
    int tx = threadIdx.x, ty = threadIdx.y;
    tile[ty][tx] = vf[(size_t)h * HSZ + (size_t)(t0 + ty) * DD + d0 + tx];
    __syncthreads();
    float v = tile[tx][ty];
    __nv_bfloat16 hh = __float2bfloat16(v);
    __nv_bfloat16 ll = __float2bfloat16(v - __bfloat162float(hh));
    size_t o = (size_t)h * HSZ + (size_t)(d0 + ty) * SQ + t0 + tx;
    vthi[o] = hh; vtlo[o] = ll;
}

// ------------------- mma.sync GEMM (3-stage cp.async, 1 sync/chunk) ----------
#define GPITCH 40
#define GSZ (128*GPITCH*2)              // 10240 B / matrix
#define GSTG (4*GSZ)                    // 40960 B / stage
#define G_SMEM (3*GSTG)                 // 122880 B

__device__ __forceinline__ void gemm_prefetch(
    uint32_t sbs, int tid, int m0, int n0, int ch,
    const __nv_bfloat16* Ahi, const __nv_bfloat16* Alo,
    const __nv_bfloat16* Whi, const __nv_bfloat16* Wlo)
{
#pragma unroll
    for (int q = 0; q < 8; q++) {
        int id = q * 256 + tid;
        int mat = id >> 9, rem = id & 511, row = rem >> 2, col = rem & 3;
        const __nv_bfloat16* g =
            (mat == 0 ? Ahi : mat == 1 ? Alo : mat == 2 ? Whi : Wlo)
            + (size_t)((mat < 2 ? m0 : n0) + row) * EE + ch * 32 + col * 8;
        CPA16(sbs + mat * GSZ + row * (GPITCH * 2) + col * 16, g);
    }
}

__global__ void __launch_bounds__(256) gemm_mma(
    const __nv_bfloat16* __restrict__ Ahi, const __nv_bfloat16* __restrict__ Alo,
    const __nv_bfloat16* __restrict__ Whi, const __nv_bfloat16* __restrict__ Wlo,
    const float* __restrict__ bias, float* __restrict__ C,
    __nv_bfloat16* __restrict__ Chi, __nv_bfloat16* __restrict__ Clo, float scale)
{
    extern __shared__ char sm[];
    uint32_t sb = smem_u32(sm);
    int tid = threadIdx.x, wid = tid >> 5, lane = tid & 31;
    int wm = wid & 3, wn = wid >> 2;
    int m0 = blockIdx.y * 128, n0 = blockIdx.x * 128;
    int l15 = lane & 15, lh = lane >> 4;

    float acc[2][8][4] = {};

    gemm_prefetch(sb, tid, m0, n0, 0, Ahi, Alo, Whi, Wlo); CPC();
    gemm_prefetch(sb + GSTG, tid, m0, n0, 1, Ahi, Alo, Whi, Wlo); CPC();

    for (int ch = 0; ch < 16; ch++) {
        if (ch == 15) { CPW(0); } else { CPW(1); }
        __syncthreads();
        if (ch + 2 < 16) {
            gemm_prefetch(sb + ((ch + 2) % 3) * GSTG, tid, m0, n0, ch + 2, Ahi, Alo, Whi, Wlo);
            CPC();
        }
        uint32_t sbs = sb + (ch % 3) * GSTG;
#pragma unroll
        for (int ks = 0; ks < 2; ks++) {
            uint32_t ah[2][4], al[2][4];
#pragma unroll
            for (int mt = 0; mt < 2; mt++) {
                uint32_t addr = sbs + (wm * 32 + mt * 16 + l15) * (GPITCH * 2)
                              + (ks * 16 + 8 * lh) * 2;
                LDSM4(ah[mt][0], ah[mt][1], ah[mt][2], ah[mt][3], addr);
                addr += GSZ;
                LDSM4(al[mt][0], al[mt][1], al[mt][2], al[mt][3], addr);
            }
#pragma unroll
            for (int jt = 0; jt < 4; jt++) {
                uint32_t addr = sbs + 2 * GSZ + (wn * 64 + jt * 16 + l15) * (GPITCH * 2)
                              + (ks * 16 + 8 * lh) * 2;
                uint32_t h0, h1, h2, h3, l0, l1, l2, l3;
                LDSM4(h0, h1, h2, h3, addr);
                LDSM4(l0, l1, l2, l3, addr + GSZ);
                uint32_t b0[2] = {h0, h2}, b1[2] = {h1, h3};
                uint32_t c0[2] = {l0, l2}, c1[2] = {l1, l3};
#pragma unroll
                for (int mt = 0; mt < 2; mt++) {
                    MMA16816(acc[mt][2*jt],   ah[mt], b0);
                    MMA16816(acc[mt][2*jt],   al[mt], b0);
                    MMA16816(acc[mt][2*jt],   ah[mt], c0);
                    MMA16816(acc[mt][2*jt+1], ah[mt], b1);
                    MMA16816(acc[mt][2*jt+1], al[mt], b1);
                    MMA16816(acc[mt][2*jt+1], ah[mt], c1);
                }
            }
        }
    }

    int r = lane >> 2, c2 = (lane & 3) * 2;
#pragma unroll
    for (int mt = 0; mt < 2; mt++) {
        size_t rbase = (size_t)(m0 + wm * 32 + mt * 16 + r) * EE + n0 + wn * 64;
#pragma unroll
        for (int j = 0; j < 8; j++) {
            float b0 = __ldg(bias + n0 + wn * 64 + j * 8 + c2);
            float b1 = __ldg(bias + n0 + wn * 64 + j * 8 + c2 + 1);
            float y00 = (acc[mt][j][0] + b0) * scale, y01 = (acc[mt][j][1] + b1) * scale;
            float y10 = (acc[mt][j][2] + b0) * scale, y11 = (acc[mt][j][3] + b1) * scale;
            if (Chi) {
                __nv_bfloat162 h0 = __floats2bfloat162_rn(y00, y01);
                __nv_bfloat162 l0 = __floats2bfloat162_rn(y00 - __bfloat162float(h0.x),
                                                          y01 - __bfloat162float(h0.y));
                __nv_bfloat162 h1 = __floats2bfloat162_rn(y10, y11);
                __nv_bfloat162 l1 = __floats2bfloat162_rn(y10 - __bfloat162float(h1.x),
                                                          y11 - __bfloat162float(h1.y));
                *(uint32_t*)(Chi + rbase + j * 8 + c2)          = *(uint32_t*)&h0;
                *(uint32_t*)(Clo + rbase + j * 8 + c2)          = *(uint32_t*)&l0;
                *(uint32_t*)(Chi + rbase + 8 * EE + j * 8 + c2) = *(uint32_t*)&h1;
                *(uint32_t*)(Clo + rbase + 8 * EE + j * 8 + c2) = *(uint32_t*)&l1;
            } else {
                *(float2*)(C + rbase + j * 8 + c2)          = make_float2(y00, y01);
                *(float2*)(C + rbase + 8 * EE + j * 8 + c2) = make_float2(y10, y11);
            }
        }
    }
}

// ------------------- mma.sync flash attention (3-stage, 1 sync/chunk, 2 CTA/SM) --
#define APITCH 72
#define AMSZ (64*APITCH*2)              // 9216 B / matrix
#define ASTG (4*AMSZ)                   // 36864 B / stage
#define A_SMEM (3*ASTG)                 // 110592 B

__device__ __forceinline__ void attn_prefetch(
    uint32_t sbs, int tid, size_t hb, int t0,
    const __nv_bfloat16* khi, const __nv_bfloat16* klo,
    const __nv_bfloat16* vth, const __nv_bfloat16* vtl)
{
#pragma unroll
    for (int q = 0; q < 8; q++) {
        int id = q * 256 + tid;
        int mat = id >> 9, rem = id & 511, row = rem >> 3, col = rem & 7;
        const __nv_bfloat16* g;
        if (mat == 0)      g = khi + hb + (size_t)(t0 + row) * DD + col * 8;
        else if (mat == 1) g = klo + hb + (size_t)(t0 + row) * DD + col * 8;
        else if (mat == 2) g = vth + hb + (size_t)row * SQ + t0 + col * 8;
        else               g = vtl + hb + (size_t)row * SQ + t0 + col * 8;
        CPA16(sbs + mat * AMSZ + row * (APITCH * 2) + col * 16, g);
    }
}

__global__ void __launch_bounds__(256, 2) attn_mma(
    const __nv_bfloat16* __restrict__ qhi, const __nv_bfloat16* __restrict__ qlo,
    const __nv_bfloat16* __restrict__ khi, const __nv_bfloat16* __restrict__ klo,
    const __nv_bfloat16* __restrict__ vth, const __nv_bfloat16* __restrict__ vtl,
    __nv_bfloat16* __restrict__ ohi, __nv_bfloat16* __restrict__ olo)
{
    extern __shared__ char sm[];
    uint32_t sb = smem_u32(sm);
    int tid = threadIdx.x, wid = tid >> 5, lane = tid & 31;
    int head = blockIdx.y, m0 = blockIdx.x * 128;
    const size_t hb = (size_t)head * HSZ;
    int r = lane >> 2, c2 = (lane & 3) * 2;
    int l15 = lane & 15, lh = lane >> 4;

    attn_prefetch(sb, tid, hb, 0, khi, klo, vth, vtl); CPC();
    attn_prefetch(sb + ASTG, tid, hb, 64, khi, klo, vth, vtl); CPC();

    // Q fragments (hi/lo), held in registers for all 64 KV chunks
    uint32_t qh[4][4], ql[4][4];
    {
        const __nv_bfloat16* q0h = qhi + hb + (size_t)(m0 + wid * 16) * DD;
        const __nv_bfloat16* q0l = qlo + hb + (size_t)(m0 + wid * 16) * DD;
#pragma unroll
        for (int ks = 0; ks < 4; ks++)
#pragma unroll
            for (int j = 0; j < 4; j++) {
                int rr = r + (j & 1) * 8;
                int kk = ks * 16 + c2 + (j >> 1) * 8;
                qh[ks][j] = *(const uint32_t*)(q0h + rr * DD + kk);
                ql[ks][j] = *(const uint32_t*)(q0l + rr * DD + kk);
            }
    }

    float oacc[8][4] = {};
    float rs0 = 0.f, rs1 = 0.f;

    for (int t = 0; t < 64; t++) {
        if (t == 63) { CPW(0); } else { CPW(1); }
        __syncthreads();
        if (t + 2 < 64) {
            attn_prefetch(sb + ((t + 2) % 3) * ASTG, tid, hb, (t + 2) * 64, khi, klo, vth, vtl);
            CPC();
        }
        uint32_t sbs = sb + (t % 3) * ASTG;

        // ---- S = Q @ K^T (3-term), per-jt B loads ----
        float sacc[8][4] = {};
#pragma unroll
        for (int ks = 0; ks < 4; ks++) {
#pragma unroll
            for (int jt = 0; jt < 4; jt++) {
                uint32_t addr = sbs + (jt * 16 + l15) * (APITCH * 2) + (ks * 16 + 8 * lh) * 2;
                uint32_t h0, h1, h2, h3, l0, l1, l2, l3;
                LDSM4(h0, h1, h2, h3, addr);
                LDSM4(l0, l1, l2, l3, addr + AMSZ);
                uint32_t b0[2] = {h0, h2}, b1[2] = {h1, h3};
                uint32_t c0[2] = {l0, l2}, c1[2] = {l1, l3};
                MMA16816(sacc[2*jt],   qh[ks], b0);
                MMA16816(sacc[2*jt],   ql[ks], b0);
                MMA16816(sacc[2*jt],   qh[ks], c0);
                MMA16816(sacc[2*jt+1], qh[ks], b1);
                MMA16816(sacc[2*jt+1], ql[ks], b1);
                MMA16816(sacc[2*jt+1], qh[ks], c1);
            }
        }

        // ---- softmax + PV interleaved per 16-kv slab (tt) ----
#pragma unroll
        for (int tt = 0; tt < 4; tt++) {
            float e0[4], e1[4];
#pragma unroll
            for (int e = 0; e < 4; e++) { e0[e] = __expf(sacc[2*tt][e]); e1[e] = __expf(sacc[2*tt+1][e]); }
            rs0 += e0[0] + e0[1] + e1[0] + e1[1];
            rs1 += e0[2] + e0[3] + e1[2] + e1[3];
            uint32_t pa[4], pl[4];
            {
                __nv_bfloat162 h, l;
                h = __floats2bfloat162_rn(e0[0], e0[1]);
                l = __floats2bfloat162_rn(e0[0] - __bfloat162float(h.x), e0[1] - __bfloat162float(h.y));
                pa[0] = *(uint32_t*)&h; pl[0] = *(uint32_t*)&l;
                h = __floats2bfloat162_rn(e0[2], e0[3]);
                l = __floats2bfloat162_rn(e0[2] - __bfloat162float(h.x), e0[3] - __bfloat162float(h.y));
                pa[1] = *(uint32_t*)&h; pl[1] = *(uint32_t*)&l;
                h = __floats2bfloat162_rn(e1[0], e1[1]);
                l = __floats2bfloat162_rn(e1[0] - __bfloat162float(h.x), e1[1] - __bfloat162float(h.y));
                pa[2] = *(uint32_t*)&h; pl[2] = *(uint32_t*)&l;
                h = __floats2bfloat162_rn(e1[2], e1[3]);
                l = __floats2bfloat162_rn(e1[2] - __bfloat162float(h.x), e1[3] - __bfloat162float(h.y));
                pa[3] = *(uint32_t*)&h; pl[3] = *(uint32_t*)&l;
            }
#pragma unroll
            for (int jt = 0; jt < 4; jt++) {
                uint32_t addr = sbs + 2 * AMSZ + (jt * 16 + l15) * (APITCH * 2)
                              + (tt * 16 + 8 * lh) * 2;
                uint32_t h0, h1, h2, h3, l0, l1, l2, l3;
                LDSM4(h0, h1, h2, h3, addr);
                LDSM4(l0, l1, l2, l3, addr + AMSZ);
                uint32_t b0[2] = {h0, h2}, b1[2] = {h1, h3};
                uint32_t c0[2] = {l0, l2}, c1[2] = {l1, l3};
                MMA16816(oacc[2*jt],   pa, b0);
                MMA16816(oacc[2*jt],   pl, b0);
                MMA16816(oacc[2*jt],   pa, c0);
                MMA16816(oacc[2*jt+1], pa, b1);
                MMA16816(oacc[2*jt+1], pl, b1);
                MMA16816(oacc[2*jt+1], pa, c1);
            }
        }
    }

    // rowsum reduce across the quad
    rs0 += __shfl_xor_sync(0xffffffffu, rs0, 1);
    rs0 += __shfl_xor_sync(0xffffffffu, rs0, 2);
    rs1 += __shfl_xor_sync(0xffffffffu, rs1, 1);
    rs1 += __shfl_xor_sync(0xffffffffu, rs1, 2);
    float i0 = 1.f / rs0, i1 = 1.f / rs1;

    size_t rbase = hb + (size_t)(m0 + wid * 16 + r) * DD;
#pragma unroll
    for (int j = 0; j < 8; j++) {
        float y00 = oacc[j][0] * i0, y01 = oacc[j][1] * i0;
        float y10 = oacc[j][2] * i1, y11 = oacc[j][3] * i1;
        __nv_bfloat162 h0 = __floats2bfloat162_rn(y00, y01);
        __nv_bfloat162 l0 = __floats2bfloat162_rn(y00 - __bfloat162float(h0.x),
                                                  y01 - __bfloat162float(h0.y));
        __nv_bfloat162 h1 = __floats2bfloat162_rn(y10, y11);
        __nv_bfloat162 l1 = __floats2bfloat162_rn(y10 - __bfloat162float(h1.x),
                                                  y11 - __bfloat162float(h1.y));
        *(uint32_t*)(ohi + rbase + j * 8 + c2)          = *(uint32_t*)&h0;
        *(uint32_t*)(olo + rbase + j * 8 + c2)          = *(uint32_t*)&l0;
        *(uint32_t*)(ohi + rbase + 8 * DD + j * 8 + c2) = *(uint32_t*)&h1;
        *(uint32_t*)(olo + rbase + 8 * DD + j * 8 + c2) = *(uint32_t*)&l1;
    }
}

// ------------------- host -------------------
extern "C" void kernel_launch(void* const* d_in, const int* in_sizes, int n_in,
                              void* d_out, int out_size) {
    const float* Q    = (const float*)d_in[0];
    const float* K    = (const float*)d_in[1];
    const float* V    = (const float*)d_in[2];
    const float* Wqk  = (const float*)d_in[3];
    const float* bqk  = (const float*)d_in[4];
    const float* Wv   = (const float*)d_in[5];
    const float* bv   = (const float*)d_in[6];
    const float* Wout = (const float*)d_in[7];
    const float* bout = (const float*)d_in[8];
    float* out = (float*)d_out;

    float *vf;
    __nv_bfloat16 *Qhi,*Qlo,*Khi,*Klo,*Vhi,*Vlo,*W1h,*W1l,*W2h,*W2l,*W3h,*W3l;
    __nv_bfloat16 *qhi,*qlo,*khi,*klo,*vth,*vtl,*ohi,*olo;
    cudaGetSymbolAddress((void**)&vf, g_vf);
    cudaGetSymbolAddress((void**)&Qhi, g_Qhi); cudaGetSymbolAddress((void**)&Qlo, g_Qlo);
    cudaGetSymbolAddress((void**)&Khi, g_Khi); cudaGetSymbolAddress((void**)&Klo, g_Klo);
    cudaGetSymbolAddress((void**)&Vhi, g_Vhi); cudaGetSymbolAddress((void**)&Vlo, g_Vlo);
    cudaGetSymbolAddress((void**)&W1h, g_W1hi); cudaGetSymbolAddress((void**)&W1l, g_W1lo);
    cudaGetSymbolAddress((void**)&W2h, g_W2hi); cudaGetSymbolAddress((void**)&W2l, g_W2lo);
    cudaGetSymbolAddress((void**)&W3h, g_W3hi); cudaGetSymbolAddress((void**)&W3l, g_W3lo);
    cudaGetSymbolAddress((void**)&qhi, g_qhi); cudaGetSymbolAddress((void**)&qlo, g_qlo);
    cudaGetSymbolAddress((void**)&khi, g_khi); cudaGetSymbolAddress((void**)&klo, g_klo);
    cudaGetSymbolAddress((void**)&vth, g_vthi); cudaGetSymbolAddress((void**)&vtl, g_vtlo);
    cudaGetSymbolAddress((void**)&ohi, g_ohi); cudaGetSymbolAddress((void**)&olo, g_olo);

    cudaFuncSetAttribute(gemm_mma, cudaFuncAttributeMaxDynamicSharedMemorySize, G_SMEM);
    cudaFuncSetAttribute(attn_mma, cudaFuncAttributeMaxDynamicSharedMemorySize, A_SMEM);

    const int TB = 256;
    split4x3<<<dim3(TOT/4/TB, 3), TB>>>((const float4*)Q, (uint2*)Qhi, (uint2*)Qlo,
                                        (const float4*)K, (uint2*)Khi, (uint2*)Klo,
                                        (const float4*)V, (uint2*)Vhi, (uint2*)Vlo);
    split4x3<<<dim3(EE*EE/4/TB, 3), TB>>>((const float4*)Wqk,  (uint2*)W1h, (uint2*)W1l,
                                          (const float4*)Wv,   (uint2*)W2h, (uint2*)W2l,
                                          (const float4*)Wout, (uint2*)W3h, (uint2*)W3l);

    dim3 gg(EE/128, SQ/128);   // (4, 32)
    gemm_mma<<<gg, TB, G_SMEM>>>(Qhi, Qlo, W1h, W1l, bqk, nullptr, qhi, qlo, 0.125f);
    gemm_mma<<<gg, TB, G_SMEM>>>(Khi, Klo, W1h, W1l, bqk, nullptr, khi, klo, 1.f);
    gemm_mma<<<gg, TB, G_SMEM>>>(Vhi, Vlo, W2h, W2l, bv,  vf, nullptr, nullptr, 1.f);

    vtrans_split<<<dim3(SQ/32, DD/32, HH), dim3(32,32)>>>(vf, vth, vtl);

    attn_mma<<<dim3(SQ/128, HH), TB, A_SMEM>>>(qhi, qlo, khi, klo, vth, vtl, ohi, olo);

    gemm_mma<<<gg, TB, G_SMEM>>>(ohi, olo, W3h, W3l, bout, out, nullptr, nullptr, 1.f);
}